// round 12
// baseline (speedup 1.0000x reference)
#include <cuda_runtime.h>
#include <stdint.h>

// fftshift ∘ ifftshift on even dims (320,320): net roll ≡ 0 → identity.
// Task is a 104.86 MB D2D copy, measured at 7.74 TB/s combined traffic
// (96.7% of 8 TB/s HBM spec). Floor = 26.2 µs kernel-side.
//
// R10: winning 256-bit access width, geometry flipped to maximum thread-level
// parallelism: 1 LDG.256 + 1 STG.256 per thread, 512-thread blocks,
// 6400 blocks × 512 × 1 == n8 exact cover. Shortest body (min regs, max occ),
// 2× independent warps feeding the DRAM request queues.

struct __align__(32) f32x8 { float v[8]; };

__device__ __forceinline__ f32x8 ldg256_ef(const f32x8* p) {
    f32x8 r;
    asm volatile(
        "ld.global.nc.L1::evict_first.v8.f32 {%0,%1,%2,%3,%4,%5,%6,%7}, [%8];"
        : "=f"(r.v[0]), "=f"(r.v[1]), "=f"(r.v[2]), "=f"(r.v[3]),
          "=f"(r.v[4]), "=f"(r.v[5]), "=f"(r.v[6]), "=f"(r.v[7])
        : "l"(p));
    return r;
}

__device__ __forceinline__ void stg256(f32x8* p, const f32x8& r) {
    asm volatile(
        "st.global.v8.f32 [%0], {%1,%2,%3,%4,%5,%6,%7,%8};"
        :: "l"(p),
           "f"(r.v[0]), "f"(r.v[1]), "f"(r.v[2]), "f"(r.v[3]),
           "f"(r.v[4]), "f"(r.v[5]), "f"(r.v[6]), "f"(r.v[7])
        : "memory");
}

__global__ void copy_v8x1_kernel(const f32x8* __restrict__ src,
                                 f32x8* __restrict__ dst) {
    const int i = blockIdx.x * blockDim.x + threadIdx.x;
    f32x8 a = ldg256_ef(src + i);
    stg256(dst + i, a);
}

// Fallback tail (not hit for this problem's exact-cover size).
__global__ void copy_f4_tail_kernel(const float4* __restrict__ src,
                                    float4* __restrict__ dst,
                                    int start, int n4) {
    int i = start + blockIdx.x * blockDim.x + threadIdx.x;
    if (i < n4) dst[i] = src[i];
}

extern "C" void kernel_launch(void* const* d_in, const int* in_sizes, int n_in,
                              void* d_out, int out_size) {
    int n4 = out_size / 4;          // float4 count: 6,553,600
    int n8 = n4 / 2;                // f32x8 count:  3,276,800

    const int threads = 512;
    int blocks = n8 / threads;      // 6400: exact cover
    if (blocks > 0) {
        copy_v8x1_kernel<<<blocks, threads>>>((const f32x8*)d_in[0],
                                              (f32x8*)d_out);
    }
    int done4 = blocks * threads * 2;  // float4s covered
    int rem4 = n4 - done4;
    if (rem4 > 0) {
        const int tthreads = 256;
        copy_f4_tail_kernel<<<(rem4 + tthreads - 1) / tthreads, tthreads>>>(
            (const float4*)d_in[0], (float4*)d_out, done4, n4);
    }
}